// round 1
// baseline (speedup 1.0000x reference)
#include <cuda_runtime.h>
#include <cstdint>

// Problem constants (from reference: x (256,18,18,512), W (18,512,512), b (18,512), idx (18))
#define KB_ 256
#define O_ 18
#define J_ 18
#define DIM 512
#define M_TOTAL (KB_ * J_)   // 4608 rows per o-GEMM

#define BM 128
#define BN 128
#define BK 16
#define ST 20                // smem row stride in uint32 (BK + 4 pad) -> conflict-free frag loads
#define NKT (DIM / BK)       // 32 k-tiles
#define SCALE_F 0.044194173824159216f  // 1/sqrt(512) * LR_MUL

__device__ int g_sel[J_];

__global__ void build_sel_kernel(const int* __restrict__ idx, int n) {
    int t = threadIdx.x;
    if (t < J_) g_sel[t] = 0;
    __syncthreads();
    if (t < n) {
        int v = idx[t];
        if (v >= 0 && v < J_) g_sel[v] = 1;
    }
}

__device__ __forceinline__ uint32_t f2tf32(float f) {
    uint32_t u;
    asm("cvt.rna.tf32.f32 %0, %1;" : "=r"(u) : "f"(f));
    return u;
}

__global__ __launch_bounds__(256, 2)
void dirnet_gemm_kernel(const float* __restrict__ x, const float* __restrict__ W,
                        const float* __restrict__ bias, float* __restrict__ out) {
    const int o   = blockIdx.z;
    const int mt  = blockIdx.y;
    const int nt  = blockIdx.x;
    const int tid = threadIdx.x;
    const int lane = tid & 31;
    const int wid  = tid >> 5;
    const int g  = lane >> 2;   // group id (0..7)
    const int t4 = lane & 3;    // thread-in-group (0..3)
    const int wm = wid >> 2;    // warp m (0..1) -> 64 rows
    const int wn = wid & 3;     // warp n (0..3) -> 32 cols

    __shared__ uint32_t sA[2][BM * ST];
    __shared__ uint32_t sB[2][BN * ST];

    // Each thread loads 2 float4 for A and 2 float4 for B per k-tile.
    int aOff[2], bOff[2], sOff[2];
    #pragma unroll
    for (int it = 0; it < 2; it++) {
        int f   = it * 256 + tid;
        int row = f >> 2;        // 0..127
        int c4  = f & 3;         // 0..3 (float4 column)
        int m   = mt * BM + row;
        int kb  = m / J_;
        int j   = m - kb * J_;
        aOff[it] = ((kb * O_ + o) * J_ + j) * DIM + c4 * 4;
        bOff[it] = o * (DIM * DIM) + (nt * BN + row) * DIM + c4 * 4;
        sOff[it] = row * ST + c4 * 4;
    }

    float4 ra[2], rb[2];
    #pragma unroll
    for (int it = 0; it < 2; it++) {
        ra[it] = *reinterpret_cast<const float4*>(x + aOff[it]);
        rb[it] = *reinterpret_cast<const float4*>(W + bOff[it]);
    }
    #pragma unroll
    for (int it = 0; it < 2; it++) {
        uint4 ua = make_uint4(f2tf32(ra[it].x), f2tf32(ra[it].y), f2tf32(ra[it].z), f2tf32(ra[it].w));
        uint4 ub = make_uint4(f2tf32(rb[it].x), f2tf32(rb[it].y), f2tf32(rb[it].z), f2tf32(rb[it].w));
        *reinterpret_cast<uint4*>(&sA[0][sOff[it]]) = ua;
        *reinterpret_cast<uint4*>(&sB[0][sOff[it]]) = ub;
    }
    __syncthreads();

    float acc[4][4][4];
    #pragma unroll
    for (int a = 0; a < 4; a++)
        #pragma unroll
        for (int b = 0; b < 4; b++)
            #pragma unroll
            for (int c = 0; c < 4; c++) acc[a][b][c] = 0.f;

    const int mBase = wm * 64;
    const int nBase = wn * 32;

    for (int kt = 0; kt < NKT; kt++) {
        const int cur = kt & 1;

        if (kt < NKT - 1) {
            #pragma unroll
            for (int it = 0; it < 2; it++) {
                ra[it] = *reinterpret_cast<const float4*>(x + aOff[it] + (kt + 1) * BK);
                rb[it] = *reinterpret_cast<const float4*>(W + bOff[it] + (kt + 1) * BK);
            }
        }

        #pragma unroll
        for (int ks = 0; ks < 2; ks++) {
            const int k0 = ks * 8;
            uint32_t af[4][4], bf[4][2];
            #pragma unroll
            for (int mf = 0; mf < 4; mf++) {
                int r = (mBase + mf * 16 + g) * ST + k0 + t4;
                af[mf][0] = sA[cur][r];
                af[mf][1] = sA[cur][r + 8 * ST];
                af[mf][2] = sA[cur][r + 4];
                af[mf][3] = sA[cur][r + 8 * ST + 4];
            }
            #pragma unroll
            for (int nf = 0; nf < 4; nf++) {
                int r = (nBase + nf * 8 + g) * ST + k0 + t4;
                bf[nf][0] = sB[cur][r];
                bf[nf][1] = sB[cur][r + 4];
            }
            #pragma unroll
            for (int mf = 0; mf < 4; mf++)
                #pragma unroll
                for (int nf = 0; nf < 4; nf++) {
                    asm volatile(
                        "mma.sync.aligned.m16n8k8.row.col.f32.tf32.tf32.f32 "
                        "{%0,%1,%2,%3}, {%4,%5,%6,%7}, {%8,%9}, {%0,%1,%2,%3};\n"
                        : "+f"(acc[mf][nf][0]), "+f"(acc[mf][nf][1]),
                          "+f"(acc[mf][nf][2]), "+f"(acc[mf][nf][3])
                        : "r"(af[mf][0]), "r"(af[mf][1]), "r"(af[mf][2]), "r"(af[mf][3]),
                          "r"(bf[nf][0]), "r"(bf[nf][1]));
                }
        }

        if (kt < NKT - 1) {
            const int nxt = cur ^ 1;
            #pragma unroll
            for (int it = 0; it < 2; it++) {
                uint4 ua = make_uint4(f2tf32(ra[it].x), f2tf32(ra[it].y), f2tf32(ra[it].z), f2tf32(ra[it].w));
                uint4 ub = make_uint4(f2tf32(rb[it].x), f2tf32(rb[it].y), f2tf32(rb[it].z), f2tf32(rb[it].w));
                *reinterpret_cast<uint4*>(&sA[nxt][sOff[it]]) = ua;
                *reinterpret_cast<uint4*>(&sB[nxt][sOff[it]]) = ub;
            }
            __syncthreads();
        }
    }

    // Epilogue: y = acc*SCALE + b[o]  (rows in idx), else passthrough x.
    const float* bRow = bias + o * DIM;
    #pragma unroll
    for (int mf = 0; mf < 4; mf++) {
        #pragma unroll
        for (int half = 0; half < 2; half++) {
            int mloc = mBase + mf * 16 + g + half * 8;
            int m  = mt * BM + mloc;
            int kb = m / J_;
            int j  = m - kb * J_;
            int rowOff = ((kb * O_ + o) * J_ + j) * DIM;
            int selv = g_sel[j];
            #pragma unroll
            for (int nf = 0; nf < 4; nf++) {
                int n = nt * BN + nBase + nf * 8 + t4 * 2;
                float v0, v1;
                if (selv) {
                    v0 = acc[mf][nf][half * 2 + 0] * SCALE_F + bRow[n];
                    v1 = acc[mf][nf][half * 2 + 1] * SCALE_F + bRow[n + 1];
                } else {
                    v0 = x[rowOff + n];
                    v1 = x[rowOff + n + 1];
                }
                *reinterpret_cast<float2*>(out + rowOff + n) = make_float2(v0, v1);
            }
        }
    }
}

extern "C" void kernel_launch(void* const* d_in, const int* in_sizes, int n_in,
                              void* d_out, int out_size) {
    const float* x   = (const float*)d_in[0];
    const float* W   = (const float*)d_in[1];
    const float* b   = (const float*)d_in[2];
    const int*   idx = (const int*)d_in[3];
    float* out = (float*)d_out;

    build_sel_kernel<<<1, 32>>>(idx, in_sizes[3]);

    dim3 grid(DIM / BN, M_TOTAL / BM, O_);
    dirnet_gemm_kernel<<<grid, 256>>>(x, W, b, out);
}